// round 1
// baseline (speedup 1.0000x reference)
#include <cuda_runtime.h>
#include <cstdint>

#define Dd 128
#define NN 50000
#define NE 625000
#define TM 64
#define KC 16
#define XPAD 132   // 128 + 4 pad (keeps 16B alignment, breaks bank conflicts)
#define APAD 17

// Scratch: per-node projections P = node_attr @ W1[0:128], Q = node_attr @ W1[128:256]
__device__ float g_P[(size_t)NN * Dd];
__device__ float g_Q[(size_t)NN * Dd];
__device__ int g_idx64;

// ---------------------------------------------------------------------------
// Detect whether edge_world_index is int64 or int32.
// If the buffer is really int32, interpreting pairs as int64 yields
// lo + hi*2^32 with hi ~ Uniform[0,50000) -> almost surely >= NN somewhere.
// If really int64, all values are valid node ids in [0, NN).
// ---------------------------------------------------------------------------
__global__ void detect_idx_kernel(const void* __restrict__ idx) {
    if (threadIdx.x == 0 && blockIdx.x == 0) {
        const long long* p = (const long long*)idx;
        int ok = 1;
        for (int i = 0; i < 1024; ++i) {
            long long v = p[i];
            if (v < 0 || v >= (long long)NN) { ok = 0; break; }
        }
        g_idx64 = ok;
    }
}

// ---------------------------------------------------------------------------
// Node projection: P = X @ W1a, Q = X @ W1b   (X: [NN,128], W blocks 128x128)
// One block = 64 nodes. X tile resident in smem, W streamed in KC chunks.
// ---------------------------------------------------------------------------
__global__ __launch_bounds__(256) void node_proj_kernel(
    const float* __restrict__ node_attr,
    const float* __restrict__ W1) {
    __shared__ float Xs[TM][XPAD];
    __shared__ float Ws[KC][Dd];

    const int block0 = blockIdx.x * TM;
    const int tid = threadIdx.x;

    // Load X tile (64 x 128 floats) via float4
    for (int i = tid; i < TM * (Dd / 4); i += 256) {
        int r = i >> 5;        // /32
        int c4 = i & 31;
        int gr = block0 + r;
        float4 v = make_float4(0.f, 0.f, 0.f, 0.f);
        if (gr < NN) v = ((const float4*)(node_attr + (size_t)gr * Dd))[c4];
        *(float4*)&Xs[r][c4 * 4] = v;
    }
    __syncthreads();

    const int ty = tid >> 4, tx = tid & 15;
    const int rm = ty * 4, cn = tx * 8;

    #pragma unroll 1
    for (int half = 0; half < 2; ++half) {
        float acc[4][8];
        #pragma unroll
        for (int i = 0; i < 4; ++i)
            #pragma unroll
            for (int j = 0; j < 8; ++j) acc[i][j] = 0.f;

        const float* Wbase = W1 + (size_t)half * Dd * Dd;

        for (int kc = 0; kc < Dd; kc += KC) {
            for (int i = tid; i < KC * (Dd / 4); i += 256) {
                int r = i >> 5, c4 = i & 31;
                ((float4*)&Ws[r][0])[c4] =
                    ((const float4*)(Wbase + (size_t)(kc + r) * Dd))[c4];
            }
            __syncthreads();
            #pragma unroll
            for (int k = 0; k < KC; ++k) {
                float a0 = Xs[rm + 0][kc + k];
                float a1 = Xs[rm + 1][kc + k];
                float a2 = Xs[rm + 2][kc + k];
                float a3 = Xs[rm + 3][kc + k];
                float4 bv0 = *(const float4*)&Ws[k][cn];
                float4 bv1 = *(const float4*)&Ws[k][cn + 4];
                float bb[8] = {bv0.x, bv0.y, bv0.z, bv0.w, bv1.x, bv1.y, bv1.z, bv1.w};
                #pragma unroll
                for (int j = 0; j < 8; ++j) {
                    acc[0][j] = fmaf(a0, bb[j], acc[0][j]);
                    acc[1][j] = fmaf(a1, bb[j], acc[1][j]);
                    acc[2][j] = fmaf(a2, bb[j], acc[2][j]);
                    acc[3][j] = fmaf(a3, bb[j], acc[3][j]);
                }
            }
            __syncthreads();
        }

        float* dst = half ? g_Q : g_P;
        #pragma unroll
        for (int i = 0; i < 4; ++i) {
            int gr = block0 + rm + i;
            if (gr < NN) {
                *(float4*)(dst + (size_t)gr * Dd + cn) =
                    make_float4(acc[i][0], acc[i][1], acc[i][2], acc[i][3]);
                *(float4*)(dst + (size_t)gr * Dd + cn + 4) =
                    make_float4(acc[i][4], acc[i][5], acc[i][6], acc[i][7]);
            }
        }
    }
}

// ---------------------------------------------------------------------------
// Fused edge kernel. One block = 64 edges.
//   acc  = P[s] + Q[r] + b1 + edge_attr @ W1c    (GEMM1, K streamed)
//   H    = relu(acc)                              (smem)
//   acc2 = b2 + H @ W2                            (GEMM2)
//   out  = layernorm(acc2) * gamma + beta         (warp-per-row)
// ---------------------------------------------------------------------------
__global__ __launch_bounds__(256) void edge_fused_kernel(
    const float* __restrict__ edge_attr,
    const void* __restrict__ idx,
    const float* __restrict__ W1,
    const float* __restrict__ b1,
    const float* __restrict__ W2,
    const float* __restrict__ b2,
    const float* __restrict__ gamma,
    const float* __restrict__ beta,
    float* __restrict__ out) {
    __shared__ float Hs[TM][XPAD];   // 33.8 KB
    __shared__ float As[TM][APAD];   // 4.4 KB
    __shared__ float Ws[KC][Dd];     // 8 KB

    const int e0 = blockIdx.x * TM;
    const int tid = threadIdx.x;
    const int ty = tid >> 4, tx = tid & 15;
    const int rm = ty * 4, cn = tx * 8;

    const int is64 = g_idx64;
    const long long* idx64 = (const long long*)idx;
    const int* idx32 = (const int*)idx;

    float acc[4][8];

    // Init accumulators: P[sender] + Q[receiver] + b1 (gathers hit L2)
    float4 bb0 = *(const float4*)(b1 + cn);
    float4 bb1 = *(const float4*)(b1 + cn + 4);
    #pragma unroll
    for (int i = 0; i < 4; ++i) {
        int e = e0 + rm + i;
        if (e < NE) {
            int s, r;
            if (is64) { s = (int)idx64[e]; r = (int)idx64[NE + e]; }
            else      { s = idx32[e];      r = idx32[NE + e]; }
            const float4* Pp = (const float4*)(g_P + (size_t)s * Dd + cn);
            const float4* Qp = (const float4*)(g_Q + (size_t)r * Dd + cn);
            float4 p0 = Pp[0], p1 = Pp[1];
            float4 q0 = Qp[0], q1 = Qp[1];
            acc[i][0] = p0.x + q0.x + bb0.x;
            acc[i][1] = p0.y + q0.y + bb0.y;
            acc[i][2] = p0.z + q0.z + bb0.z;
            acc[i][3] = p0.w + q0.w + bb0.w;
            acc[i][4] = p1.x + q1.x + bb1.x;
            acc[i][5] = p1.y + q1.y + bb1.y;
            acc[i][6] = p1.z + q1.z + bb1.z;
            acc[i][7] = p1.w + q1.w + bb1.w;
        } else {
            #pragma unroll
            for (int j = 0; j < 8; ++j) acc[i][j] = 0.f;
        }
    }

    // ---- Stage 1: += edge_attr @ W1c ----
    for (int kc = 0; kc < Dd; kc += KC) {
        {   // load A chunk [64][16]: thread -> (row = tid/4, float4 col = tid%4)
            int r = tid >> 2;
            int c4 = tid & 3;
            int e = e0 + r;
            float4 v = make_float4(0.f, 0.f, 0.f, 0.f);
            if (e < NE) v = *(const float4*)(edge_attr + (size_t)e * Dd + kc + c4 * 4);
            As[r][c4 * 4 + 0] = v.x;
            As[r][c4 * 4 + 1] = v.y;
            As[r][c4 * 4 + 2] = v.z;
            As[r][c4 * 4 + 3] = v.w;
        }
        for (int i = tid; i < KC * (Dd / 4); i += 256) {
            int r = i >> 5, c4 = i & 31;
            ((float4*)&Ws[r][0])[c4] =
                ((const float4*)(W1 + (size_t)(2 * Dd + kc + r) * Dd))[c4];
        }
        __syncthreads();
        #pragma unroll
        for (int k = 0; k < KC; ++k) {
            float a0 = As[rm + 0][k];
            float a1 = As[rm + 1][k];
            float a2 = As[rm + 2][k];
            float a3 = As[rm + 3][k];
            float4 bv0 = *(const float4*)&Ws[k][cn];
            float4 bv1 = *(const float4*)&Ws[k][cn + 4];
            float bbv[8] = {bv0.x, bv0.y, bv0.z, bv0.w, bv1.x, bv1.y, bv1.z, bv1.w};
            #pragma unroll
            for (int j = 0; j < 8; ++j) {
                acc[0][j] = fmaf(a0, bbv[j], acc[0][j]);
                acc[1][j] = fmaf(a1, bbv[j], acc[1][j]);
                acc[2][j] = fmaf(a2, bbv[j], acc[2][j]);
                acc[3][j] = fmaf(a3, bbv[j], acc[3][j]);
            }
        }
        __syncthreads();
    }

    // ReLU -> Hs
    #pragma unroll
    for (int i = 0; i < 4; ++i) {
        *(float4*)&Hs[rm + i][cn] = make_float4(
            fmaxf(acc[i][0], 0.f), fmaxf(acc[i][1], 0.f),
            fmaxf(acc[i][2], 0.f), fmaxf(acc[i][3], 0.f));
        *(float4*)&Hs[rm + i][cn + 4] = make_float4(
            fmaxf(acc[i][4], 0.f), fmaxf(acc[i][5], 0.f),
            fmaxf(acc[i][6], 0.f), fmaxf(acc[i][7], 0.f));
    }

    // Re-init accumulators with b2
    {
        float4 c0 = *(const float4*)(b2 + cn);
        float4 c1 = *(const float4*)(b2 + cn + 4);
        #pragma unroll
        for (int i = 0; i < 4; ++i) {
            acc[i][0] = c0.x; acc[i][1] = c0.y; acc[i][2] = c0.z; acc[i][3] = c0.w;
            acc[i][4] = c1.x; acc[i][5] = c1.y; acc[i][6] = c1.z; acc[i][7] = c1.w;
        }
    }
    __syncthreads();

    // ---- Stage 2: += H @ W2 ----
    for (int kc = 0; kc < Dd; kc += KC) {
        for (int i = tid; i < KC * (Dd / 4); i += 256) {
            int r = i >> 5, c4 = i & 31;
            ((float4*)&Ws[r][0])[c4] =
                ((const float4*)(W2 + (size_t)(kc + r) * Dd))[c4];
        }
        __syncthreads();
        #pragma unroll
        for (int k = 0; k < KC; ++k) {
            float a0 = Hs[rm + 0][kc + k];
            float a1 = Hs[rm + 1][kc + k];
            float a2 = Hs[rm + 2][kc + k];
            float a3 = Hs[rm + 3][kc + k];
            float4 bv0 = *(const float4*)&Ws[k][cn];
            float4 bv1 = *(const float4*)&Ws[k][cn + 4];
            float bbv[8] = {bv0.x, bv0.y, bv0.z, bv0.w, bv1.x, bv1.y, bv1.z, bv1.w};
            #pragma unroll
            for (int j = 0; j < 8; ++j) {
                acc[0][j] = fmaf(a0, bbv[j], acc[0][j]);
                acc[1][j] = fmaf(a1, bbv[j], acc[1][j]);
                acc[2][j] = fmaf(a2, bbv[j], acc[2][j]);
                acc[3][j] = fmaf(a3, bbv[j], acc[3][j]);
            }
        }
        __syncthreads();
    }

    // Write pre-LN result back into Hs (all Hs reads done at loop's last sync)
    #pragma unroll
    for (int i = 0; i < 4; ++i) {
        *(float4*)&Hs[rm + i][cn] =
            make_float4(acc[i][0], acc[i][1], acc[i][2], acc[i][3]);
        *(float4*)&Hs[rm + i][cn + 4] =
            make_float4(acc[i][4], acc[i][5], acc[i][6], acc[i][7]);
    }
    __syncthreads();

    // ---- LayerNorm: one warp per row, 8 rows per warp ----
    const int warp = tid >> 5, lane = tid & 31;
    float4 g0 = *(const float4*)(gamma + lane * 4);
    float4 bt0 = *(const float4*)(beta + lane * 4);
    for (int r = warp; r < TM; r += 8) {
        float4 v = *(const float4*)&Hs[r][lane * 4];
        float s = v.x + v.y + v.z + v.w;
        float s2 = v.x * v.x + v.y * v.y + v.z * v.z + v.w * v.w;
        #pragma unroll
        for (int off = 16; off >= 1; off >>= 1) {
            s  += __shfl_xor_sync(0xFFFFFFFFu, s, off);
            s2 += __shfl_xor_sync(0xFFFFFFFFu, s2, off);
        }
        float mu = s * (1.f / 128.f);
        float var = s2 * (1.f / 128.f) - mu * mu;
        float inv = rsqrtf(var + 1e-5f);
        int e = e0 + r;
        if (e < NE) {
            float4 o;
            o.x = (v.x - mu) * inv * g0.x + bt0.x;
            o.y = (v.y - mu) * inv * g0.y + bt0.y;
            o.z = (v.z - mu) * inv * g0.z + bt0.z;
            o.w = (v.w - mu) * inv * g0.w + bt0.w;
            *(float4*)(out + (size_t)e * Dd + lane * 4) = o;
        }
    }
}

// ---------------------------------------------------------------------------
extern "C" void kernel_launch(void* const* d_in, const int* in_sizes, int n_in,
                              void* d_out, int out_size) {
    const float* node_attr = (const float*)d_in[0];
    const void*  eidx      = d_in[1];
    const float* edge_attr = (const float*)d_in[2];
    const float* W1        = (const float*)d_in[3];
    const float* b1        = (const float*)d_in[4];
    const float* W2        = (const float*)d_in[5];
    const float* b2        = (const float*)d_in[6];
    const float* gamma     = (const float*)d_in[7];
    const float* beta      = (const float*)d_in[8];
    float* out = (float*)d_out;

    detect_idx_kernel<<<1, 32>>>(eidx);

    int nblocks_node = (NN + TM - 1) / TM;
    node_proj_kernel<<<nblocks_node, 256>>>(node_attr, W1);

    int nblocks_edge = (NE + TM - 1) / TM;
    edge_fused_kernel<<<nblocks_edge, 256>>>(edge_attr, eidx, W1, b1, W2, b2,
                                             gamma, beta, out);
}

// round 8
// speedup vs baseline: 2.6965x; 2.6965x over previous
#include <cuda_runtime.h>
#include <cuda_bf16.h>
#include <cstdint>
#include <cstring>

#define Dd 128
#define NN 50000
#define NE 625000
#define RS 132                       // smem A row stride in bf16 elems (pad vs conflicts)
#define SMEM_BYTES (128 * RS * 2 * 2 + 2048)   // hi+lo planes + LN reduction

// ---------------------------------------------------------------------------
// scratch (static device memory; no runtime allocation)
// ---------------------------------------------------------------------------
__device__ float g_P[(size_t)NN * Dd];
__device__ float g_Q[(size_t)NN * Dd];
// Pre-baked B fragments in mma.m16n8k16 lane layout.
// [matrix 0..3 = W1a,W1b,W1c,W2][hi/lo][kstep 0..7][npair 0..7][lane 0..31]
// uint4 = {b0(nt=2*npair), b1(nt), b0(nt+1), b1(nt+1)}
__device__ uint4 g_Wfrag[4][2][8][8][32];
__device__ int g_idx64;

// ---------------------------------------------------------------------------
// helpers
// ---------------------------------------------------------------------------
__device__ __forceinline__ uint32_t pk(float x, float y) {
    __nv_bfloat162 h = __float22bfloat162_rn(make_float2(x, y));
    uint32_t u;
    memcpy(&u, &h, 4);
    return u;   // low 16 bits = x
}

__device__ __forceinline__ void mma16816(float d[4], const uint32_t a[4],
                                         uint32_t b0, uint32_t b1) {
    asm volatile(
        "mma.sync.aligned.m16n8k16.row.col.f32.bf16.bf16.f32 "
        "{%0,%1,%2,%3}, {%4,%5,%6,%7}, {%8,%9}, {%0,%1,%2,%3};"
        : "+f"(d[0]), "+f"(d[1]), "+f"(d[2]), "+f"(d[3])
        : "r"(a[0]), "r"(a[1]), "r"(a[2]), "r"(a[3]), "r"(b0), "r"(b1));
}

// split-bf16 GEMM: acc += A_tile(128x128 fp32, hi/lo bf16 planes) @ W[mat]
// products: Ahi*Whi + Ahi*Wlo (shared A-frag load) + Alo*Whi.
// Warp tile = 32 rows x 64 cols.
__device__ __forceinline__ void gemm3(float (&acc)[2][8][4],
                                      const __nv_bfloat16* __restrict__ Ahi,
                                      const __nv_bfloat16* __restrict__ Alo,
                                      int mat, int m0, int nw, int g, int t, int lane) {
    // pass 0: A = hi plane, both hi and lo W images (one A load, two B streams)
    #pragma unroll
    for (int ks = 0; ks < 8; ++ks) {
        uint32_t a[2][4];
        #pragma unroll
        for (int mt = 0; mt < 2; ++mt) {
            const __nv_bfloat16* r0 = Ahi + (size_t)(m0 + mt * 16 + g) * RS + ks * 16 + 2 * t;
            const __nv_bfloat16* r1 = r0 + 8 * RS;
            a[mt][0] = *(const uint32_t*)r0;
            a[mt][1] = *(const uint32_t*)r1;
            a[mt][2] = *(const uint32_t*)(r0 + 8);
            a[mt][3] = *(const uint32_t*)(r1 + 8);
        }
        #pragma unroll
        for (int p = 0; p < 2; ++p) {
            const uint4 (*B)[8][32] = g_Wfrag[mat][p];
            #pragma unroll
            for (int np = 0; np < 4; ++np) {
                uint4 bv = B[ks][nw * 4 + np][lane];
                mma16816(acc[0][2 * np],     a[0], bv.x, bv.y);
                mma16816(acc[0][2 * np + 1], a[0], bv.z, bv.w);
                mma16816(acc[1][2 * np],     a[1], bv.x, bv.y);
                mma16816(acc[1][2 * np + 1], a[1], bv.z, bv.w);
            }
        }
    }
    // pass 1: A = lo plane, W hi image
    #pragma unroll
    for (int ks = 0; ks < 8; ++ks) {
        uint32_t a[2][4];
        #pragma unroll
        for (int mt = 0; mt < 2; ++mt) {
            const __nv_bfloat16* r0 = Alo + (size_t)(m0 + mt * 16 + g) * RS + ks * 16 + 2 * t;
            const __nv_bfloat16* r1 = r0 + 8 * RS;
            a[mt][0] = *(const uint32_t*)r0;
            a[mt][1] = *(const uint32_t*)r1;
            a[mt][2] = *(const uint32_t*)(r0 + 8);
            a[mt][3] = *(const uint32_t*)(r1 + 8);
        }
        const uint4 (*B)[8][32] = g_Wfrag[mat][0];
        #pragma unroll
        for (int np = 0; np < 4; ++np) {
            uint4 bv = B[ks][nw * 4 + np][lane];
            mma16816(acc[0][2 * np],     a[0], bv.x, bv.y);
            mma16816(acc[0][2 * np + 1], a[0], bv.z, bv.w);
            mma16816(acc[1][2 * np],     a[1], bv.x, bv.y);
            mma16816(acc[1][2 * np + 1], a[1], bv.z, bv.w);
        }
    }
}

// load [128 x 128] fp32 tile, split into bf16 hi/lo planes in smem (row-major, stride RS)
__device__ __forceinline__ void cvt_tile(__nv_bfloat16* __restrict__ Ahi,
                                         __nv_bfloat16* __restrict__ Alo,
                                         const float* __restrict__ src,
                                         int r0, int rmax, int tid) {
    for (int i = tid; i < 128 * 32; i += 256) {
        int rr = i >> 5, c4 = i & 31;
        int gr = r0 + rr;
        float4 v = make_float4(0.f, 0.f, 0.f, 0.f);
        if (gr < rmax) v = *(const float4*)(src + (size_t)gr * Dd + c4 * 4);
        __nv_bfloat162 h01 = __float22bfloat162_rn(make_float2(v.x, v.y));
        float2 f01 = __bfloat1622float2(h01);
        __nv_bfloat162 h23 = __float22bfloat162_rn(make_float2(v.z, v.w));
        float2 f23 = __bfloat1622float2(h23);
        uint32_t* dh = (uint32_t*)(Ahi + (size_t)rr * RS) + c4 * 2;
        uint32_t* dl = (uint32_t*)(Alo + (size_t)rr * RS) + c4 * 2;
        dh[0] = pk(v.x, v.y);       // identical bits to h01
        dh[1] = pk(v.z, v.w);
        dl[0] = pk(v.x - f01.x, v.y - f01.y);
        dl[1] = pk(v.z - f23.x, v.w - f23.y);
    }
}

// ---------------------------------------------------------------------------
// setup kernels
// ---------------------------------------------------------------------------
__global__ void detect_idx_kernel(const void* __restrict__ idx) {
    if (threadIdx.x == 0 && blockIdx.x == 0) {
        const long long* p = (const long long*)idx;
        int ok = 1;
        for (int i = 0; i < 1024; ++i) {
            long long v = p[i];
            if (v < 0 || v >= (long long)NN) { ok = 0; break; }
        }
        g_idx64 = ok;
    }
}

__global__ void weights_kernel(const float* __restrict__ W1, const float* __restrict__ W2) {
    int m = blockIdx.x;   // 0:W1a 1:W1b 2:W1c 3:W2
    const float* src = (m < 3) ? (W1 + (size_t)m * Dd * Dd) : W2;
    for (int idx = threadIdx.x; idx < 2 * 8 * 8 * 32; idx += blockDim.x) {
        int p = idx >> 11;          // 0 hi, 1 lo
        int rem = idx & 2047;
        int ks = rem >> 8;
        int np = (rem >> 5) & 7;
        int lane = rem & 31;
        int g = lane >> 2, t = lane & 3;
        uint32_t vals[4];
        #pragma unroll
        for (int half = 0; half < 2; ++half) {
            int n = (np * 2 + half) * 8 + g;
            float w[4];
            w[0] = src[(size_t)(ks * 16 + 2 * t) * Dd + n];
            w[1] = src[(size_t)(ks * 16 + 2 * t + 1) * Dd + n];
            w[2] = src[(size_t)(ks * 16 + 2 * t + 8) * Dd + n];
            w[3] = src[(size_t)(ks * 16 + 2 * t + 9) * Dd + n];
            float s[4];
            #pragma unroll
            for (int j = 0; j < 4; ++j) {
                float hv = __bfloat162float(__float2bfloat16(w[j]));
                s[j] = p ? (w[j] - hv) : w[j];
            }
            vals[half * 2 + 0] = pk(s[0], s[1]);
            vals[half * 2 + 1] = pk(s[2], s[3]);
        }
        g_Wfrag[m][p][ks][np][lane] = make_uint4(vals[0], vals[1], vals[2], vals[3]);
    }
}

// ---------------------------------------------------------------------------
// node projection: P = X @ W1a, Q = X @ W1b (128-node tiles)
// ---------------------------------------------------------------------------
__global__ __launch_bounds__(256, 2) void node_kernel(const float* __restrict__ node_attr) {
    extern __shared__ char smem[];
    __nv_bfloat16* Ahi = (__nv_bfloat16*)smem;
    __nv_bfloat16* Alo = Ahi + 128 * RS;

    const int tid = threadIdx.x;
    const int lane = tid & 31, w = tid >> 5;
    const int g = lane >> 2, t = lane & 3;
    const int m0 = (w & 3) * 32, nw = w >> 2, nc0 = nw * 64;
    const int r0 = blockIdx.x * 128;

    cvt_tile(Ahi, Alo, node_attr, r0, NN, tid);
    __syncthreads();

    float acc[2][8][4];
    #pragma unroll 1
    for (int mat = 0; mat < 2; ++mat) {
        #pragma unroll
        for (int mt = 0; mt < 2; ++mt)
            #pragma unroll
            for (int nt = 0; nt < 8; ++nt)
                #pragma unroll
                for (int j = 0; j < 4; ++j) acc[mt][nt][j] = 0.f;

        gemm3(acc, Ahi, Alo, mat, m0, nw, g, t, lane);

        float* dst = mat ? g_Q : g_P;
        #pragma unroll
        for (int mt = 0; mt < 2; ++mt) {
            #pragma unroll
            for (int h = 0; h < 2; ++h) {
                int gr = r0 + m0 + mt * 16 + h * 8 + g;
                if (gr < NN) {
                    #pragma unroll
                    for (int nt = 0; nt < 8; ++nt) {
                        int c = nc0 + nt * 8 + 2 * t;
                        *(float2*)(dst + (size_t)gr * Dd + c) =
                            make_float2(acc[mt][nt][h * 2], acc[mt][nt][h * 2 + 1]);
                    }
                }
            }
        }
    }
}

// ---------------------------------------------------------------------------
// fused edge kernel
// ---------------------------------------------------------------------------
__global__ __launch_bounds__(256, 2) void edge_kernel(
    const float* __restrict__ edge_attr,
    const void* __restrict__ idx,
    const float* __restrict__ b1,
    const float* __restrict__ b2,
    const float* __restrict__ gamma,
    const float* __restrict__ beta,
    float* __restrict__ out) {
    extern __shared__ char smem[];
    __nv_bfloat16* Ahi = (__nv_bfloat16*)smem;
    __nv_bfloat16* Alo = Ahi + 128 * RS;
    float* redS  = (float*)(smem + (size_t)128 * RS * 4);   // [128][2]
    float* redS2 = redS + 256;

    const int tid = threadIdx.x;
    const int lane = tid & 31, w = tid >> 5;
    const int g = lane >> 2, t = lane & 3;
    const int m0 = (w & 3) * 32, nw = w >> 2, nc0 = nw * 64;
    const int e0 = blockIdx.x * 128;
    const int is64 = g_idx64;

    cvt_tile(Ahi, Alo, edge_attr, e0, NE, tid);
    __syncthreads();

    float acc[2][8][4];
    #pragma unroll
    for (int mt = 0; mt < 2; ++mt)
        #pragma unroll
        for (int nt = 0; nt < 8; ++nt)
            #pragma unroll
            for (int j = 0; j < 4; ++j) acc[mt][nt][j] = 0.f;

    // GEMM1: edge_attr @ W1c
    gemm3(acc, Ahi, Alo, 2, m0, nw, g, t, lane);

    // + P[sender] + Q[receiver] + b1, then ReLU (per-fragment gathers, L2 hits)
    #pragma unroll
    for (int mt = 0; mt < 2; ++mt) {
        #pragma unroll
        for (int h = 0; h < 2; ++h) {
            int e = e0 + m0 + mt * 16 + h * 8 + g;
            if (e < NE) {
                int s, rv;
                if (is64) {
                    const long long* pI = (const long long*)idx;
                    s = (int)pI[e]; rv = (int)pI[NE + e];
                } else {
                    const int* pI = (const int*)idx;
                    s = pI[e]; rv = pI[NE + e];
                }
                const float* Pp = g_P + (size_t)s * Dd;
                const float* Qp = g_Q + (size_t)rv * Dd;
                #pragma unroll
                for (int nt = 0; nt < 8; ++nt) {
                    int c = nc0 + nt * 8 + 2 * t;
                    float2 pv = *(const float2*)(Pp + c);
                    float2 qv = *(const float2*)(Qp + c);
                    float2 bv = *(const float2*)(b1 + c);
                    acc[mt][nt][h * 2 + 0] += pv.x + qv.x + bv.x;
                    acc[mt][nt][h * 2 + 1] += pv.y + qv.y + bv.y;
                }
            }
        }
    }
    #pragma unroll
    for (int mt = 0; mt < 2; ++mt)
        #pragma unroll
        for (int nt = 0; nt < 8; ++nt)
            #pragma unroll
            for (int j = 0; j < 4; ++j) acc[mt][nt][j] = fmaxf(acc[mt][nt][j], 0.f);

    __syncthreads();   // all warps done reading edge A planes

    // store H = relu(...) as hi/lo bf16 back into the A planes
    #pragma unroll
    for (int mt = 0; mt < 2; ++mt) {
        #pragma unroll
        for (int h = 0; h < 2; ++h) {
            int row = m0 + mt * 16 + h * 8 + g;
            #pragma unroll
            for (int nt = 0; nt < 8; ++nt) {
                int c = nc0 + nt * 8 + 2 * t;
                float x0 = acc[mt][nt][h * 2], x1 = acc[mt][nt][h * 2 + 1];
                __nv_bfloat162 hh = __float22bfloat162_rn(make_float2(x0, x1));
                float2 hf = __bfloat1622float2(hh);
                *(uint32_t*)(Ahi + (size_t)row * RS + c) = pk(x0, x1);
                *(uint32_t*)(Alo + (size_t)row * RS + c) = pk(x0 - hf.x, x1 - hf.y);
            }
        }
    }
    __syncthreads();

    #pragma unroll
    for (int mt = 0; mt < 2; ++mt)
        #pragma unroll
        for (int nt = 0; nt < 8; ++nt)
            #pragma unroll
            for (int j = 0; j < 4; ++j) acc[mt][nt][j] = 0.f;

    // GEMM2: H @ W2
    gemm3(acc, Ahi, Alo, 3, m0, nw, g, t, lane);

    // LayerNorm: add b2, row-sum via quad shuffle + cross-n-warp smem reduction
    #pragma unroll
    for (int mt = 0; mt < 2; ++mt) {
        #pragma unroll
        for (int h = 0; h < 2; ++h) {
            int row = m0 + mt * 16 + h * 8 + g;
            float s = 0.f, s2 = 0.f;
            #pragma unroll
            for (int nt = 0; nt < 8; ++nt) {
                int c = nc0 + nt * 8 + 2 * t;
                float2 bv = *(const float2*)(b2 + c);
                float v0 = acc[mt][nt][h * 2] + bv.x;
                float v1 = acc[mt][nt][h * 2 + 1] + bv.y;
                acc[mt][nt][h * 2] = v0;
                acc[mt][nt][h * 2 + 1] = v1;
                s += v0 + v1;
                s2 += v0 * v0 + v1 * v1;
            }
            s  += __shfl_xor_sync(0xFFFFFFFFu, s, 1);
            s  += __shfl_xor_sync(0xFFFFFFFFu, s, 2);
            s2 += __shfl_xor_sync(0xFFFFFFFFu, s2, 1);
            s2 += __shfl_xor_sync(0xFFFFFFFFu, s2, 2);
            if (t == 0) {
                redS[row * 2 + nw] = s;
                redS2[row * 2 + nw] = s2;
            }
        }
    }
    __syncthreads();

    #pragma unroll
    for (int mt = 0; mt < 2; ++mt) {
        #pragma unroll
        for (int h = 0; h < 2; ++h) {
            int row = m0 + mt * 16 + h * 8 + g;
            int e = e0 + row;
            if (e < NE) {
                float S  = redS[row * 2] + redS[row * 2 + 1];
                float S2 = redS2[row * 2] + redS2[row * 2 + 1];
                float mu = S * (1.f / 128.f);
                float var = S2 * (1.f / 128.f) - mu * mu;
                float inv = rsqrtf(var + 1e-5f);
                #pragma unroll
                for (int nt = 0; nt < 8; ++nt) {
                    int c = nc0 + nt * 8 + 2 * t;
                    float2 gv = *(const float2*)(gamma + c);
                    float2 bv = *(const float2*)(beta + c);
                    float2 o;
                    o.x = (acc[mt][nt][h * 2] - mu) * inv * gv.x + bv.x;
                    o.y = (acc[mt][nt][h * 2 + 1] - mu) * inv * gv.y + bv.y;
                    *(float2*)(out + (size_t)e * Dd + c) = o;
                }
            }
        }
    }
}

// ---------------------------------------------------------------------------
extern "C" void kernel_launch(void* const* d_in, const int* in_sizes, int n_in,
                              void* d_out, int out_size) {
    const float* node_attr = (const float*)d_in[0];
    const void*  eidx      = d_in[1];
    const float* edge_attr = (const float*)d_in[2];
    const float* W1        = (const float*)d_in[3];
    const float* b1        = (const float*)d_in[4];
    const float* W2        = (const float*)d_in[5];
    const float* b2        = (const float*)d_in[6];
    const float* gamma     = (const float*)d_in[7];
    const float* beta      = (const float*)d_in[8];
    float* out = (float*)d_out;

    cudaFuncSetAttribute(node_kernel, cudaFuncAttributeMaxDynamicSharedMemorySize, SMEM_BYTES);
    cudaFuncSetAttribute(edge_kernel, cudaFuncAttributeMaxDynamicSharedMemorySize, SMEM_BYTES);

    detect_idx_kernel<<<1, 32>>>(eidx);
    weights_kernel<<<4, 256>>>(W1, W2);

    node_kernel<<<(NN + 127) / 128, 256, SMEM_BYTES>>>(node_attr);
    edge_kernel<<<(NE + 127) / 128, 256, SMEM_BYTES>>>(edge_attr, eidx, b1, b2,
                                                       gamma, beta, out);
}